// round 11
// baseline (speedup 1.0000x reference)
#include <cuda_runtime.h>
#include <cuda_fp16.h>
#include <math.h>

#define NN 100000
#define NE 3200000
#define FIN 32
#define HD 64
#define NL 4
#define NA 6158
#define NG 64
#define WPAD 68

// ---------------- scratch (device globals; no allocation allowed) -------------
__device__ int   d_flag;
__device__ int   d_src[NE];
__device__ int   d_dst[NE];
__device__ int   d_batch32[NN];
__device__ int   d_deg[NN];
__device__ int   d_rowptr[NN + 1];
__device__ int   d_cursor[NN];
__device__ int   d_csr[NE];
__device__ float d_invdeg[NN];
__device__ float d_h0[NN * HD];
__device__ float d_h1[NN * HD];
__device__ __half2 d_hh[NN * 32];
__device__ float d_agg[NN * HD];
__device__ float d_gsum[NG * HD];
__device__ int   d_gcnt[NG];
__device__ int   d_part[256];

// ---------------- f32x2 packed-FMA helpers -------------------------------------
__device__ __forceinline__ unsigned long long pack2(float x) {
    unsigned long long r;
    asm("mov.b64 %0, {%1, %1};" : "=l"(r) : "f"(x));
    return r;
}
__device__ __forceinline__ void ffma2(unsigned long long& d,
                                      unsigned long long a,
                                      unsigned long long b) {
    asm("fma.rn.f32x2 %0, %1, %2, %0;" : "+l"(d) : "l"(a), "l"(b));
}
__device__ __forceinline__ void unpack2(unsigned long long v, float& lo, float& hi) {
    asm("mov.b64 {%0, %1}, %2;" : "=f"(lo), "=f"(hi) : "l"(v));
}

// ---------------- encoder: h0 = relu(x @ W_enc^T + b_enc) + zero accumulators --
__global__ void k_encoder(const float* __restrict__ x,
                          const float* __restrict__ Wenc,
                          const float* __restrict__ benc) {
    __shared__ float Ws[FIN * HD];
    __shared__ float bs[HD];
    int t = threadIdx.x;
    int gid = blockIdx.x * blockDim.x + t;
    if (gid < NN) d_deg[gid] = 0;
    if (gid < NG) d_gcnt[gid] = 0;
    if (gid < NG * HD) d_gsum[gid] = 0.f;

    for (int i = t; i < HD * FIN; i += blockDim.x) {
        int j = i / FIN, k = i % FIN;
        Ws[k * HD + j] = Wenc[i];
    }
    if (t < HD) bs[t] = benc[t];
    __syncthreads();
    if (gid >= NN * 32) return;
    int n = gid >> 5, j2 = gid & 31;
    int j = 2 * j2;
    const float* xr = x + n * FIN;
    float a0 = bs[j], a1 = bs[j + 1];
#pragma unroll
    for (int k = 0; k < FIN; k += 4) {
        float4 xv = *(const float4*)(xr + k);
        float2 w0 = *(const float2*)(&Ws[k * HD + j]);
        float2 w1 = *(const float2*)(&Ws[(k + 1) * HD + j]);
        float2 w2 = *(const float2*)(&Ws[(k + 2) * HD + j]);
        float2 w3 = *(const float2*)(&Ws[(k + 3) * HD + j]);
        a0 += xv.x * w0.x + xv.y * w1.x + xv.z * w2.x + xv.w * w3.x;
        a1 += xv.x * w0.y + xv.y * w1.y + xv.z * w2.y + xv.w * w3.y;
    }
    a0 = fmaxf(a0, 0.f);
    a1 = fmaxf(a1, 0.f);
    ((float2*)d_h0)[gid] = make_float2(a0, a1);
    d_hh[gid] = __floats2half2_rn(a0, a1);
}

// convert edges + degree count; dtype detection done block-locally (warp ballot)
__global__ void k_convert_edges(const void* edge) {
    __shared__ int sflag;
    if (threadIdx.x < 32) {
        const unsigned int* w = (const unsigned int*)edge;
        unsigned int m0 = __ballot_sync(0xffffffffu, w[2 * threadIdx.x + 1] == 0u);
        unsigned int m1 = __ballot_sync(0xffffffffu, w[2 * (threadIdx.x + 32) + 1] == 0u);
        if (threadIdx.x == 0) {
            int f = (__popc(m0) + __popc(m1) >= 60) ? 1 : 0;
            sflag = f;
            if (blockIdx.x == 0) d_flag = f;   // for k_scan_c (batch conversion)
        }
    }
    __syncthreads();
    int i = blockIdx.x * blockDim.x + threadIdx.x;
    if (i >= 2 * NE) return;
    int v;
    if (sflag) v = (int)((const long long*)edge)[i];
    else       v = ((const int*)edge)[i];
    if (i < NE) d_src[i] = v;
    else        { d_dst[i - NE] = v; atomicAdd(&d_deg[v], 1); }
}

// ---------------- CSR build (scan over degrees) --------------------------------
__global__ void k_scan_a() {
    __shared__ int ts[256];
    int b = blockIdx.x, t = threadIdx.x;
    int base = b * 1024 + t * 4;
    int v[4];
    int s = 0;
#pragma unroll
    for (int j = 0; j < 4; j++) {
        int idx = base + j;
        v[j] = (idx < NN) ? d_deg[idx] : 0;
        s += v[j];
    }
    ts[t] = s;
    __syncthreads();
    for (int off = 1; off < 256; off <<= 1) {
        int x = (t >= off) ? ts[t - off] : 0;
        __syncthreads();
        ts[t] += x;
        __syncthreads();
    }
    int run = ts[t] - s;
#pragma unroll
    for (int j = 0; j < 4; j++) {
        int idx = base + j;
        if (idx < NN) d_rowptr[idx] = run;
        run += v[j];
    }
    if (t == 255) d_part[b] = ts[255];
}

// scan finalize + invdeg + batch + graph counts (smem histogram, few atomics)
__global__ void k_scan_c(const void* batch) {
    __shared__ int ps[128];
    __shared__ int hist[NG];
    int t = threadIdx.x;
    if (t < NG) hist[t] = 0;
    int orig = (t < 98) ? d_part[t] : 0;
    if (t < 128) ps[t] = orig;
    __syncthreads();
    for (int off = 1; off < 128; off <<= 1) {
        int x = (t >= off && t < 128) ? ps[t - off] : 0;
        __syncthreads();
        if (t < 128) ps[t] += x;
        __syncthreads();
    }
    if (t < 128) ps[t] -= orig;   // exclusive
    __syncthreads();

    int i = blockIdx.x * blockDim.x + t;
    if (i == 0) d_rowptr[NN] = NE;
    if (i < NN) {
        int r = d_rowptr[i] + ps[i >> 10];
        d_rowptr[i] = r;
        d_cursor[i] = r;
        d_invdeg[i] = 1.0f / fmaxf((float)d_deg[i], 1.0f);
        int b;
        if (d_flag) b = (int)((const long long*)batch)[i];
        else        b = ((const int*)batch)[i];
        d_batch32[i] = b;
        atomicAdd(&hist[b], 1);   // smem, sorted -> 1-2 hot counters per block
    }
    __syncthreads();
    if (t < NG) {
        int c = hist[t];
        if (c) atomicAdd(&d_gcnt[t], c);   // ~2 global atomics per block
    }
}

__global__ void k_scatter() {
    int e = blockIdx.x * blockDim.x + threadIdx.x;
    if (e >= NE) return;
    int dd = d_dst[e];
    int pos = atomicAdd(&d_cursor[dd], 1);
    d_csr[pos] = d_src[e];
}

// ---------------- aggregation: agg[n] = mean_{e: dst=n} h_fp16[src[e]] ---------
__global__ void k_aggregate() {
    int w = (blockIdx.x * blockDim.x + threadIdx.x) >> 5;
    if (w >= NN) return;
    int lane = threadIdx.x & 31;
    int beg = d_rowptr[w], end = d_rowptr[w + 1];
    const __half2* __restrict__ hp = d_hh;
    float ax0 = 0.f, ay0 = 0.f, ax1 = 0.f, ay1 = 0.f;
    int i = beg;
    for (; i + 8 <= end; i += 8) {
        int s0 = d_csr[i + 0], s1 = d_csr[i + 1], s2 = d_csr[i + 2], s3 = d_csr[i + 3];
        int s4 = d_csr[i + 4], s5 = d_csr[i + 5], s6 = d_csr[i + 6], s7 = d_csr[i + 7];
        float2 v0 = __half22float2(hp[s0 * 32 + lane]);
        float2 v1 = __half22float2(hp[s1 * 32 + lane]);
        float2 v2 = __half22float2(hp[s2 * 32 + lane]);
        float2 v3 = __half22float2(hp[s3 * 32 + lane]);
        float2 v4 = __half22float2(hp[s4 * 32 + lane]);
        float2 v5 = __half22float2(hp[s5 * 32 + lane]);
        float2 v6 = __half22float2(hp[s6 * 32 + lane]);
        float2 v7 = __half22float2(hp[s7 * 32 + lane]);
        ax0 += v0.x + v1.x + v2.x + v3.x;
        ay0 += v0.y + v1.y + v2.y + v3.y;
        ax1 += v4.x + v5.x + v6.x + v7.x;
        ay1 += v4.y + v5.y + v6.y + v7.y;
    }
    for (; i < end; i++) {
        float2 v = __half22float2(hp[d_csr[i] * 32 + lane]);
        ax0 += v.x; ay0 += v.y;
    }
    float id = d_invdeg[w];
    ((float2*)d_agg)[w * 32 + lane] = make_float2((ax0 + ax1) * id, (ay0 + ay1) * id);
}

// ---------------- layer v4: 4 nodes/thread x j-quarter -> LDS count halved ------
// p = t&63 picks node-within-wave; jq = t>>6 picks output quarter [16jq,16jq+16).
// Each broadcast LDS.128 of weights feeds 4 nodes (was 2) -> 512 LDS/thread.
__global__ void __launch_bounds__(256, 2)
k_layer(int mode, int write_hh,
        const float* __restrict__ Wl, const float* __restrict__ bl,
        const float* __restrict__ Wr) {
    const float* h    = (mode == 1) ? d_h1 : d_h0;
    float*       hout = (mode == 0) ? d_h1 : d_h0;
    __shared__ float S[2 * HD * WPAD + HD];
    float* Wls = S;
    float* Wrs = S + HD * WPAD;
    float* bls = S + 2 * HD * WPAD;
    int t = threadIdx.x;
    for (int i = t; i < HD * HD; i += 256) {
        int j = i >> 6, k = i & 63;
        Wls[k * WPAD + j] = Wl[i];
        Wrs[k * WPAD + j] = Wr[i];
    }
    if (t < HD) bls[t] = bl[t];
    __syncthreads();

    int p    = t & 63;
    int jq   = t >> 6;              // 0..3
    int base = blockIdx.x * 256;
    int n[4]; bool v[4];
#pragma unroll
    for (int w = 0; w < 4; w++) { n[w] = base + w * 64 + p; v[w] = (n[w] < NN); }

    unsigned long long acc[4][8];
    {
        const unsigned long long* bp2 = (const unsigned long long*)(bls + jq * 16);
#pragma unroll
        for (int w = 0; w < 4; w++)
#pragma unroll
            for (int q = 0; q < 8; q++) acc[w][q] = bp2[q];
    }

#pragma unroll 2
    for (int k4 = 0; k4 < 16; k4++) {
        float aS[4][4], hS[4][4];
#pragma unroll
        for (int w = 0; w < 4; w++) {
            float4 av, hv;
            if (v[w]) {
                av = ((const float4*)(d_agg + n[w] * HD))[k4];
                hv = ((const float4*)(h + n[w] * HD))[k4];
            } else {
                av = make_float4(0, 0, 0, 0); hv = av;
            }
            aS[w][0] = av.x; aS[w][1] = av.y; aS[w][2] = av.z; aS[w][3] = av.w;
            hS[w][0] = hv.x; hS[w][1] = hv.y; hS[w][2] = hv.z; hS[w][3] = hv.w;
        }
#pragma unroll
        for (int kk = 0; kk < 4; kk++) {
            int k = k4 * 4 + kk;
            const ulonglong2* __restrict__ wl =
                (const ulonglong2*)(Wls + k * WPAD + jq * 16);
            const ulonglong2* __restrict__ wr =
                (const ulonglong2*)(Wrs + k * WPAD + jq * 16);
            unsigned long long ap[4], hp2[4];
#pragma unroll
            for (int w = 0; w < 4; w++) {
                ap[w]  = pack2(aS[w][kk]);
                hp2[w] = pack2(hS[w][kk]);
            }
#pragma unroll
            for (int j2 = 0; j2 < 4; j2++) {
                ulonglong2 L = wl[j2];
                ulonglong2 R = wr[j2];
#pragma unroll
                for (int w = 0; w < 4; w++) {
                    ffma2(acc[w][2 * j2 + 0], ap[w],  L.x);
                    ffma2(acc[w][2 * j2 + 1], ap[w],  L.y);
                    ffma2(acc[w][2 * j2 + 0], hp2[w], R.x);
                    ffma2(acc[w][2 * j2 + 1], hp2[w], R.y);
                }
            }
        }
    }

    // epilogue: 4 waves of 64 nodes; stage reuses W smem (coalesced stores)
    float* stage = S;
#pragma unroll
    for (int w = 0; w < 4; w++) {
        float o[16];
#pragma unroll
        for (int q = 0; q < 8; q++) unpack2(acc[w][q], o[2 * q], o[2 * q + 1]);
        if (v[w]) {
            const float4* __restrict__ res = (const float4*)(h + n[w] * HD + jq * 16);
#pragma unroll
            for (int f = 0; f < 4; f++) {
                float4 r = res[f];
                o[4 * f + 0] = fmaxf(o[4 * f + 0], 0.f) + r.x;
                o[4 * f + 1] = fmaxf(o[4 * f + 1], 0.f) + r.y;
                o[4 * f + 2] = fmaxf(o[4 * f + 2], 0.f) + r.z;
                o[4 * f + 3] = fmaxf(o[4 * f + 3], 0.f) + r.w;
            }
        }
        __syncthreads();   // wave 0: W reads done; later: prior stage reads done
        if (v[w]) {
            float4* s4 = (float4*)(stage + p * WPAD + jq * 16);
#pragma unroll
            for (int f = 0; f < 4; f++)
                s4[f] = make_float4(o[4 * f], o[4 * f + 1], o[4 * f + 2], o[4 * f + 3]);
        }
        __syncthreads();
        // 64 nodes x 16 float4 = 1024 stores, 256 threads -> 4 iters, coalesced
        for (int i2 = t; i2 < 1024; i2 += 256) {
            int node = i2 >> 4, f = i2 & 15;
            int gn = base + w * 64 + node;
            if (gn < NN) {
                float4 vv = *(const float4*)(stage + node * WPAD + f * 4);
                *(float4*)(hout + gn * 64 + f * 4) = vv;
                if (write_hh) {
                    __half2 l2 = __floats2half2_rn(vv.x, vv.y);
                    __half2 h2 = __floats2half2_rn(vv.z, vv.w);
                    unsigned int ul = *(unsigned int*)&l2;
                    unsigned int uh = *(unsigned int*)&h2;
                    ((uint2*)d_hh)[gn * 16 + f] = make_uint2(ul, uh);
                }
            }
        }
    }
}

// ---------------- global mean pool (coalesced) ----------------------------------
__global__ void k_pool(int sel) {
    const float* __restrict__ h = sel ? d_h1 : d_h0;
    int warp = threadIdx.x >> 5, lane = threadIdx.x & 31;
    int rbase = blockIdx.x * 512 + warp * 64;
    if (rbase >= NN) return;
    int rowoff = lane >> 4;
    int f4 = lane & 15;
    float a0 = 0.f, a1 = 0.f, a2 = 0.f, a3 = 0.f;
    int cur = -1;
    for (int it = 0; it < 32; it++) {
        int row = rbase + it * 2 + rowoff;
        if (row >= NN) break;
        int b = d_batch32[row];
        if (b != cur) {
            if (cur >= 0) {
                atomicAdd(&d_gsum[cur * HD + f4 * 4 + 0], a0);
                atomicAdd(&d_gsum[cur * HD + f4 * 4 + 1], a1);
                atomicAdd(&d_gsum[cur * HD + f4 * 4 + 2], a2);
                atomicAdd(&d_gsum[cur * HD + f4 * 4 + 3], a3);
            }
            a0 = a1 = a2 = a3 = 0.f;
            cur = b;
        }
        float4 v = *(const float4*)(h + row * HD + f4 * 4);
        a0 += v.x; a1 += v.y; a2 += v.z; a3 += v.w;
    }
    if (cur >= 0) {
        atomicAdd(&d_gsum[cur * HD + f4 * 4 + 0], a0);
        atomicAdd(&d_gsum[cur * HD + f4 * 4 + 1], a1);
        atomicAdd(&d_gsum[cur * HD + f4 * 4 + 2], a2);
        atomicAdd(&d_gsum[cur * HD + f4 * 4 + 3], a3);
    }
}

// ---------------- heads: policy (blocks 0..48) + value (last block) -------------
__global__ void __launch_bounds__(128)
k_policy(const float* __restrict__ Wp, const float* __restrict__ bp,
         const float* __restrict__ Wv, const float* __restrict__ bv,
         float* __restrict__ out) {
    __shared__ float repr[NG * HD];
    int t = threadIdx.x;
    for (int i = t; i < NG * HD; i += 128) {
        int g = i >> 6;
        repr[i] = d_gsum[i] / fmaxf((float)d_gcnt[g], 1.f);
    }
    __syncthreads();

    if (blockIdx.x == gridDim.x - 1) {   // value head
        int g = t;
        if (g >= NG) return;
        float acc = 0.f;
#pragma unroll
        for (int k = 0; k < HD; k++) acc += repr[g * HD + k] * Wv[k];
        out[NG * NA + g] = tanhf(acc + bv[0]);
        return;
    }

    int a = blockIdx.x * 128 + t;
    if (a >= NA) return;
    float acc[NG];
#pragma unroll
    for (int g = 0; g < NG; g++) acc[g] = 0.f;
    const float4* __restrict__ wr = (const float4*)(Wp + a * HD);
#pragma unroll 2
    for (int k4 = 0; k4 < 16; k4++) {
        float4 w = wr[k4];
#pragma unroll
        for (int g = 0; g < NG; g++) {
            float4 r = *(const float4*)(&repr[g * HD + k4 * 4]);
            acc[g] += w.x * r.x + w.y * r.y + w.z * r.z + w.w * r.w;
        }
    }
    float bias = bp[a];
#pragma unroll
    for (int g = 0; g < NG; g++) out[g * NA + a] = acc[g] + bias;
}

// ---------------- launcher -----------------------------------------------------
extern "C" void kernel_launch(void* const* d_in, const int* in_sizes, int n_in,
                              void* d_out, int out_size) {
    const float* x     = (const float*)d_in[0];
    const void*  edge  = d_in[1];
    const void*  batch = d_in[2];
    const float* Wenc  = (const float*)d_in[3];
    const float* benc  = (const float*)d_in[4];
    const float* Wl    = (const float*)d_in[5];
    const float* bl    = (const float*)d_in[6];
    const float* Wr    = (const float*)d_in[7];
    const float* Wp    = (const float*)d_in[8];
    const float* bp    = (const float*)d_in[9];
    const float* Wv    = (const float*)d_in[10];
    const float* bv    = (const float*)d_in[11];
    float* out = (float*)d_out;

    k_encoder<<<(NN * 32 + 255) / 256, 256>>>(x, Wenc, benc);      // idx 0
    k_convert_edges<<<(2 * NE + 255) / 256, 256>>>(edge);          // idx 1
    k_scan_a<<<98, 256>>>();                                       // idx 2
    k_scan_c<<<(NN + 255) / 256, 256>>>(batch);                    // idx 3 (profiled)
    k_scatter<<<(NE + 255) / 256, 256>>>();                        // idx 4

    for (int i = 0; i < NL; i++) {
        k_aggregate<<<(NN * 32 + 255) / 256, 256>>>();
        k_layer<<<(NN + 255) / 256, 256>>>(i & 1, (i < NL - 1) ? 1 : 0,
                                           Wl + i * HD * HD, bl + i * HD,
                                           Wr + i * HD * HD);
    }

    k_pool<<<(NN + 511) / 512, 256>>>(0);   // final h is d_h0 after 4 layers
    k_policy<<<(NA + 127) / 128 + 1, 128>>>(Wp, bp, Wv, bv, out);
}

// round 12
// speedup vs baseline: 1.1115x; 1.1115x over previous
#include <cuda_runtime.h>
#include <cuda_fp16.h>
#include <math.h>

#define NN 100000
#define NE 3200000
#define FIN 32
#define HD 64
#define NL 4
#define NA 6158
#define NG 64
#define WPAD 68

// ---------------- scratch (device globals; no allocation allowed) -------------
// NOTE: d_deg is zeroed at the END of each launch (by k_pool) for the next
// graph replay; statically zero-initialized for the first call.
__device__ int   d_flag;
__device__ int   d_src[NE];
__device__ int   d_dst[NE];
__device__ int   d_batch32[NN];
__device__ int   d_deg[NN];
__device__ int   d_rowptr[NN + 1];
__device__ int   d_cursor[NN];
__device__ int   d_csr[NE];
__device__ float d_invdeg[NN];
__device__ float d_h0[NN * HD];
__device__ float d_h1[NN * HD];
__device__ __half2 d_hh[NN * 32];
__device__ float d_agg[NN * HD];
__device__ float d_gsum[NG * HD];
__device__ int   d_gcnt[NG];
__device__ int   d_part[256];

// ---------------- f32x2 packed-FMA helpers -------------------------------------
__device__ __forceinline__ unsigned long long pack2(float x) {
    unsigned long long r;
    asm("mov.b64 %0, {%1, %1};" : "=l"(r) : "f"(x));
    return r;
}
__device__ __forceinline__ void ffma2(unsigned long long& d,
                                      unsigned long long a,
                                      unsigned long long b) {
    asm("fma.rn.f32x2 %0, %1, %2, %0;" : "+l"(d) : "l"(a), "l"(b));
}
__device__ __forceinline__ void unpack2(unsigned long long v, float& lo, float& hi) {
    asm("mov.b64 {%0, %1}, %2;" : "=f"(lo), "=f"(hi) : "l"(v));
}

// convert edges + degree count; dtype detection done block-locally (warp ballot)
__global__ void k_convert_edges(const void* edge) {
    __shared__ int sflag;
    if (threadIdx.x < 32) {
        const unsigned int* w = (const unsigned int*)edge;
        unsigned int m0 = __ballot_sync(0xffffffffu, w[2 * threadIdx.x + 1] == 0u);
        unsigned int m1 = __ballot_sync(0xffffffffu, w[2 * (threadIdx.x + 32) + 1] == 0u);
        if (threadIdx.x == 0) {
            int f = (__popc(m0) + __popc(m1) >= 60) ? 1 : 0;
            sflag = f;
            if (blockIdx.x == 0) d_flag = f;   // for k_scan_c (batch conversion)
        }
    }
    __syncthreads();
    int i = blockIdx.x * blockDim.x + threadIdx.x;
    if (i >= 2 * NE) return;
    int v;
    if (sflag) v = (int)((const long long*)edge)[i];
    else       v = ((const int*)edge)[i];
    if (i < NE) d_src[i] = v;
    else        { d_dst[i - NE] = v; atomicAdd(&d_deg[v], 1); }
}

// ---------------- CSR build (scan over degrees) --------------------------------
__global__ void k_scan_a() {
    __shared__ int ts[256];
    int b = blockIdx.x, t = threadIdx.x;
    int base = b * 1024 + t * 4;
    int v[4];
    int s = 0;
#pragma unroll
    for (int j = 0; j < 4; j++) {
        int idx = base + j;
        v[j] = (idx < NN) ? d_deg[idx] : 0;
        s += v[j];
    }
    ts[t] = s;
    __syncthreads();
    for (int off = 1; off < 256; off <<= 1) {
        int x = (t >= off) ? ts[t - off] : 0;
        __syncthreads();
        ts[t] += x;
        __syncthreads();
    }
    int run = ts[t] - s;
#pragma unroll
    for (int j = 0; j < 4; j++) {
        int idx = base + j;
        if (idx < NN) d_rowptr[idx] = run;
        run += v[j];
    }
    if (t == 255) d_part[b] = ts[255];
}

// scan finalize + invdeg + batch conversion
__global__ void k_scan_c(const void* batch) {
    __shared__ int ps[128];
    int t = threadIdx.x;
    int orig = (t < 98) ? d_part[t] : 0;
    if (t < 128) ps[t] = orig;
    __syncthreads();
    for (int off = 1; off < 128; off <<= 1) {
        int x = (t >= off && t < 128) ? ps[t - off] : 0;
        __syncthreads();
        if (t < 128) ps[t] += x;
        __syncthreads();
    }
    if (t < 128) ps[t] -= orig;   // exclusive
    __syncthreads();

    int i = blockIdx.x * blockDim.x + t;
    if (i == 0) d_rowptr[NN] = NE;
    if (i >= NN) return;
    int r = d_rowptr[i] + ps[i >> 10];
    d_rowptr[i] = r;
    d_cursor[i] = r;
    d_invdeg[i] = 1.0f / fmaxf((float)d_deg[i], 1.0f);
    int b;
    if (d_flag) b = (int)((const long long*)batch)[i];
    else        b = ((const int*)batch)[i];
    d_batch32[i] = b;
}

// scatter edges into CSR; also zeroes gsum/gcnt (consumed later this launch)
__global__ void k_scatter() {
    int e = blockIdx.x * blockDim.x + threadIdx.x;
    if (e < NG * HD) d_gsum[e] = 0.f;
    if (e < NG) d_gcnt[e] = 0;
    if (e >= NE) return;
    int dd = d_dst[e];
    int pos = atomicAdd(&d_cursor[dd], 1);
    d_csr[pos] = d_src[e];
}

// ---------------- encoder: h0 = relu(x @ W_enc^T + b_enc) ----------------------
__global__ void k_encoder(const float* __restrict__ x,
                          const float* __restrict__ Wenc,
                          const float* __restrict__ benc) {
    __shared__ float Ws[FIN * HD];
    __shared__ float bs[HD];
    int t = threadIdx.x;
    int gid = blockIdx.x * blockDim.x + t;
    for (int i = t; i < HD * FIN; i += blockDim.x) {
        int j = i / FIN, k = i % FIN;
        Ws[k * HD + j] = Wenc[i];
    }
    if (t < HD) bs[t] = benc[t];
    __syncthreads();
    if (gid >= NN * 32) return;
    int n = gid >> 5, j2 = gid & 31;
    int j = 2 * j2;
    const float* xr = x + n * FIN;
    float a0 = bs[j], a1 = bs[j + 1];
#pragma unroll
    for (int k = 0; k < FIN; k += 4) {
        float4 xv = *(const float4*)(xr + k);
        float2 w0 = *(const float2*)(&Ws[k * HD + j]);
        float2 w1 = *(const float2*)(&Ws[(k + 1) * HD + j]);
        float2 w2 = *(const float2*)(&Ws[(k + 2) * HD + j]);
        float2 w3 = *(const float2*)(&Ws[(k + 3) * HD + j]);
        a0 += xv.x * w0.x + xv.y * w1.x + xv.z * w2.x + xv.w * w3.x;
        a1 += xv.x * w0.y + xv.y * w1.y + xv.z * w2.y + xv.w * w3.y;
    }
    a0 = fmaxf(a0, 0.f);
    a1 = fmaxf(a1, 0.f);
    ((float2*)d_h0)[gid] = make_float2(a0, a1);
    d_hh[gid] = __floats2half2_rn(a0, a1);
}

// ---------------- aggregation: agg[n] = mean_{e: dst=n} h_fp16[src[e]] ---------
__global__ void k_aggregate() {
    int w = (blockIdx.x * blockDim.x + threadIdx.x) >> 5;
    if (w >= NN) return;
    int lane = threadIdx.x & 31;
    int beg = d_rowptr[w], end = d_rowptr[w + 1];
    const __half2* __restrict__ hp = d_hh;
    float ax0 = 0.f, ay0 = 0.f, ax1 = 0.f, ay1 = 0.f;
    int i = beg;
    for (; i + 8 <= end; i += 8) {
        int s0 = d_csr[i + 0], s1 = d_csr[i + 1], s2 = d_csr[i + 2], s3 = d_csr[i + 3];
        int s4 = d_csr[i + 4], s5 = d_csr[i + 5], s6 = d_csr[i + 6], s7 = d_csr[i + 7];
        float2 v0 = __half22float2(hp[s0 * 32 + lane]);
        float2 v1 = __half22float2(hp[s1 * 32 + lane]);
        float2 v2 = __half22float2(hp[s2 * 32 + lane]);
        float2 v3 = __half22float2(hp[s3 * 32 + lane]);
        float2 v4 = __half22float2(hp[s4 * 32 + lane]);
        float2 v5 = __half22float2(hp[s5 * 32 + lane]);
        float2 v6 = __half22float2(hp[s6 * 32 + lane]);
        float2 v7 = __half22float2(hp[s7 * 32 + lane]);
        ax0 += v0.x + v1.x + v2.x + v3.x;
        ay0 += v0.y + v1.y + v2.y + v3.y;
        ax1 += v4.x + v5.x + v6.x + v7.x;
        ay1 += v4.y + v5.y + v6.y + v7.y;
    }
    for (; i < end; i++) {
        float2 v = __half22float2(hp[d_csr[i] * 32 + lane]);
        ax0 += v.x; ay0 += v.y;
    }
    float id = d_invdeg[w];
    ((float2*)d_agg)[w * 32 + lane] = make_float2((ax0 + ax1) * id, (ay0 + ay1) * id);
}

// ---------------- layer v3 (proven): 2 nodes/thread, split epilogue -------------
__global__ void __launch_bounds__(256, 2)
k_layer(int mode, int write_hh,
        const float* __restrict__ Wl, const float* __restrict__ bl,
        const float* __restrict__ Wr) {
    const float* h    = (mode == 1) ? d_h1 : d_h0;
    float*       hout = (mode == 0) ? d_h1 : d_h0;
    __shared__ float S[2 * HD * WPAD + HD];
    float* Wls = S;
    float* Wrs = S + HD * WPAD;
    float* bls = S + 2 * HD * WPAD;
    int t = threadIdx.x;
    for (int i = t; i < HD * HD; i += 256) {
        int j = i >> 6, k = i & 63;
        Wls[k * WPAD + j] = Wl[i];
        Wrs[k * WPAD + j] = Wr[i];
    }
    if (t < HD) bls[t] = bl[t];
    __syncthreads();

    int p    = t & 127;
    int jh   = t >> 7;
    int base = blockIdx.x * 256;
    int n0 = base + p;         // always < NN (100000 mod 256 = 160 >= 128)
    int n1 = base + 128 + p;   // guarded
    bool v1 = (n1 < NN);

    unsigned long long accA[16], accB[16];
    {
        const unsigned long long* bp2 = (const unsigned long long*)(bls + jh * 32);
#pragma unroll
        for (int q = 0; q < 16; q++) { accA[q] = bp2[q]; accB[q] = bp2[q]; }
    }

    {
        const float4* __restrict__ arA = (const float4*)(d_agg + n0 * HD);
        const float4* __restrict__ hrA = (const float4*)(h + n0 * HD);
        const float4* __restrict__ arB = (const float4*)(d_agg + n1 * HD);
        const float4* __restrict__ hrB = (const float4*)(h + n1 * HD);
#pragma unroll 2
        for (int k4 = 0; k4 < 16; k4++) {
            float4 aA = arA[k4], hA = hrA[k4];
            float4 aB, hB;
            if (v1) { aB = arB[k4]; hB = hrB[k4]; }
            else    { aB = make_float4(0, 0, 0, 0); hB = aB; }
            float aAv[4] = {aA.x, aA.y, aA.z, aA.w};
            float hAv[4] = {hA.x, hA.y, hA.z, hA.w};
            float aBv[4] = {aB.x, aB.y, aB.z, aB.w};
            float hBv[4] = {hB.x, hB.y, hB.z, hB.w};
#pragma unroll
            for (int kk = 0; kk < 4; kk++) {
                int k = k4 * 4 + kk;
                const ulonglong2* __restrict__ wl =
                    (const ulonglong2*)(Wls + k * WPAD + jh * 32);
                const ulonglong2* __restrict__ wr =
                    (const ulonglong2*)(Wrs + k * WPAD + jh * 32);
                unsigned long long aAp = pack2(aAv[kk]);
                unsigned long long hAp = pack2(hAv[kk]);
                unsigned long long aBp = pack2(aBv[kk]);
                unsigned long long hBp = pack2(hBv[kk]);
#pragma unroll
                for (int j4 = 0; j4 < 8; j4++) {
                    ulonglong2 L = wl[j4];
                    ulonglong2 R = wr[j4];
                    ffma2(accA[2 * j4 + 0], aAp, L.x);
                    ffma2(accA[2 * j4 + 1], aAp, L.y);
                    ffma2(accA[2 * j4 + 0], hAp, R.x);
                    ffma2(accA[2 * j4 + 1], hAp, R.y);
                    ffma2(accB[2 * j4 + 0], aBp, L.x);
                    ffma2(accB[2 * j4 + 1], aBp, L.y);
                    ffma2(accB[2 * j4 + 0], hBp, R.x);
                    ffma2(accB[2 * j4 + 1], hBp, R.y);
                }
            }
        }
    }

    float* stage = S;   // reuse W smem
    float o[32];

    // wave 0
#pragma unroll
    for (int q = 0; q < 16; q++) unpack2(accA[q], o[2 * q], o[2 * q + 1]);
    {
        const float4* __restrict__ res = (const float4*)(h + n0 * HD + jh * 32);
#pragma unroll
        for (int f = 0; f < 8; f++) {
            float4 r = res[f];
            o[4 * f + 0] = fmaxf(o[4 * f + 0], 0.f) + r.x;
            o[4 * f + 1] = fmaxf(o[4 * f + 1], 0.f) + r.y;
            o[4 * f + 2] = fmaxf(o[4 * f + 2], 0.f) + r.z;
            o[4 * f + 3] = fmaxf(o[4 * f + 3], 0.f) + r.w;
        }
    }
    __syncthreads();
    {
        float4* s4 = (float4*)(stage + p * WPAD + jh * 32);
#pragma unroll
        for (int f = 0; f < 8; f++)
            s4[f] = make_float4(o[4 * f], o[4 * f + 1], o[4 * f + 2], o[4 * f + 3]);
    }
    __syncthreads();
    for (int i2 = t; i2 < 2048; i2 += 256) {
        int node = i2 >> 4, f = i2 & 15;
        int gn = base + node;
        float4 vv = *(const float4*)(stage + node * WPAD + f * 4);
        *(float4*)(hout + gn * 64 + f * 4) = vv;
        if (write_hh) {
            __half2 l2 = __floats2half2_rn(vv.x, vv.y);
            __half2 h2 = __floats2half2_rn(vv.z, vv.w);
            unsigned int ul = *(unsigned int*)&l2;
            unsigned int uh = *(unsigned int*)&h2;
            ((uint2*)d_hh)[gn * 16 + f] = make_uint2(ul, uh);
        }
    }

    // wave 1
#pragma unroll
    for (int q = 0; q < 16; q++) unpack2(accB[q], o[2 * q], o[2 * q + 1]);
    if (v1) {
        const float4* __restrict__ res = (const float4*)(h + n1 * HD + jh * 32);
#pragma unroll
        for (int f = 0; f < 8; f++) {
            float4 r = res[f];
            o[4 * f + 0] = fmaxf(o[4 * f + 0], 0.f) + r.x;
            o[4 * f + 1] = fmaxf(o[4 * f + 1], 0.f) + r.y;
            o[4 * f + 2] = fmaxf(o[4 * f + 2], 0.f) + r.z;
            o[4 * f + 3] = fmaxf(o[4 * f + 3], 0.f) + r.w;
        }
    }
    __syncthreads();
    if (v1) {
        float4* s4 = (float4*)(stage + p * WPAD + jh * 32);
#pragma unroll
        for (int f = 0; f < 8; f++)
            s4[f] = make_float4(o[4 * f], o[4 * f + 1], o[4 * f + 2], o[4 * f + 3]);
    }
    __syncthreads();
    for (int i2 = t; i2 < 2048; i2 += 256) {
        int node = i2 >> 4, f = i2 & 15;
        int gn = base + 128 + node;
        if (gn < NN) {
            float4 vv = *(const float4*)(stage + node * WPAD + f * 4);
            *(float4*)(hout + gn * 64 + f * 4) = vv;
            if (write_hh) {
                __half2 l2 = __floats2half2_rn(vv.x, vv.y);
                __half2 h2 = __floats2half2_rn(vv.z, vv.w);
                unsigned int ul = *(unsigned int*)&l2;
                unsigned int uh = *(unsigned int*)&h2;
                ((uint2*)d_hh)[gn * 16 + f] = make_uint2(ul, uh);
            }
        }
    }
}

// ---------------- global mean pool (coalesced) + gcnt + deg re-zero -------------
__global__ void k_pool(int sel) {
    // zero d_deg for the NEXT graph replay (d_deg no longer needed this launch)
    int tid = blockIdx.x * blockDim.x + threadIdx.x;
    int z = tid * 2;
    if (z < NN) {
        d_deg[z] = 0;
        if (z + 1 < NN) d_deg[z + 1] = 0;
    }

    const float* __restrict__ h = sel ? d_h1 : d_h0;
    int warp = threadIdx.x >> 5, lane = threadIdx.x & 31;
    int rbase = blockIdx.x * 512 + warp * 64;
    if (rbase >= NN) return;
    int rowoff = lane >> 4;
    int f4 = lane & 15;
    float a0 = 0.f, a1 = 0.f, a2 = 0.f, a3 = 0.f;
    int cnt = 0;
    int cur = -1;
    for (int it = 0; it < 32; it++) {
        int row = rbase + it * 2 + rowoff;
        if (row >= NN) break;
        int b = d_batch32[row];
        if (b != cur) {
            if (cur >= 0) {
                atomicAdd(&d_gsum[cur * HD + f4 * 4 + 0], a0);
                atomicAdd(&d_gsum[cur * HD + f4 * 4 + 1], a1);
                atomicAdd(&d_gsum[cur * HD + f4 * 4 + 2], a2);
                atomicAdd(&d_gsum[cur * HD + f4 * 4 + 3], a3);
                if (f4 == 0) atomicAdd(&d_gcnt[cur], cnt);
            }
            a0 = a1 = a2 = a3 = 0.f;
            cnt = 0;
            cur = b;
        }
        float4 v = *(const float4*)(h + row * HD + f4 * 4);
        a0 += v.x; a1 += v.y; a2 += v.z; a3 += v.w;
        cnt++;
    }
    if (cur >= 0) {
        atomicAdd(&d_gsum[cur * HD + f4 * 4 + 0], a0);
        atomicAdd(&d_gsum[cur * HD + f4 * 4 + 1], a1);
        atomicAdd(&d_gsum[cur * HD + f4 * 4 + 2], a2);
        atomicAdd(&d_gsum[cur * HD + f4 * 4 + 3], a3);
        if (f4 == 0) atomicAdd(&d_gcnt[cur], cnt);
    }
}

// ---------------- heads: policy (blocks 0..48) + value (last block) -------------
__global__ void __launch_bounds__(128)
k_policy(const float* __restrict__ Wp, const float* __restrict__ bp,
         const float* __restrict__ Wv, const float* __restrict__ bv,
         float* __restrict__ out) {
    __shared__ float repr[NG * HD];
    int t = threadIdx.x;
    for (int i = t; i < NG * HD; i += 128) {
        int g = i >> 6;
        repr[i] = d_gsum[i] / fmaxf((float)d_gcnt[g], 1.f);
    }
    __syncthreads();

    if (blockIdx.x == gridDim.x - 1) {   // value head
        int g = t;
        if (g >= NG) return;
        float acc = 0.f;
#pragma unroll
        for (int k = 0; k < HD; k++) acc += repr[g * HD + k] * Wv[k];
        out[NG * NA + g] = tanhf(acc + bv[0]);
        return;
    }

    int a = blockIdx.x * 128 + t;
    if (a >= NA) return;
    float acc[NG];
#pragma unroll
    for (int g = 0; g < NG; g++) acc[g] = 0.f;
    const float4* __restrict__ wr = (const float4*)(Wp + a * HD);
#pragma unroll 2
    for (int k4 = 0; k4 < 16; k4++) {
        float4 w = wr[k4];
#pragma unroll
        for (int g = 0; g < NG; g++) {
            float4 r = *(const float4*)(&repr[g * HD + k4 * 4]);
            acc[g] += w.x * r.x + w.y * r.y + w.z * r.z + w.w * r.w;
        }
    }
    float bias = bp[a];
#pragma unroll
    for (int g = 0; g < NG; g++) out[g * NA + a] = acc[g] + bias;
}

// ---------------- launcher -----------------------------------------------------
extern "C" void kernel_launch(void* const* d_in, const int* in_sizes, int n_in,
                              void* d_out, int out_size) {
    const float* x     = (const float*)d_in[0];
    const void*  edge  = d_in[1];
    const void*  batch = d_in[2];
    const float* Wenc  = (const float*)d_in[3];
    const float* benc  = (const float*)d_in[4];
    const float* Wl    = (const float*)d_in[5];
    const float* bl    = (const float*)d_in[6];
    const float* Wr    = (const float*)d_in[7];
    const float* Wp    = (const float*)d_in[8];
    const float* bp    = (const float*)d_in[9];
    const float* Wv    = (const float*)d_in[10];
    const float* bv    = (const float*)d_in[11];
    float* out = (float*)d_out;

    k_convert_edges<<<(2 * NE + 255) / 256, 256>>>(edge);          // idx 0
    k_scan_a<<<98, 256>>>();                                       // idx 1
    k_scan_c<<<(NN + 255) / 256, 256>>>(batch);                    // idx 2
    k_scatter<<<(NE + 255) / 256, 256>>>();                        // idx 3 (profiled)
    k_encoder<<<(NN * 32 + 255) / 256, 256>>>(x, Wenc, benc);      // idx 4

    for (int i = 0; i < NL; i++) {
        k_aggregate<<<(NN * 32 + 255) / 256, 256>>>();
        k_layer<<<(NN + 255) / 256, 256>>>(i & 1, (i < NL - 1) ? 1 : 0,
                                           Wl + i * HD * HD, bl + i * HD,
                                           Wr + i * HD * HD);
    }

    k_pool<<<(NN + 511) / 512, 256>>>(0);   // final h is d_h0 after 4 layers
    k_policy<<<(NA + 127) / 128 + 1, 128>>>(Wp, bp, Wv, bv, out);
}

// round 13
// speedup vs baseline: 1.2006x; 1.0802x over previous
#include <cuda_runtime.h>
#include <cuda_fp16.h>
#include <math.h>

#define NN 100000
#define NE 3200000
#define FIN 32
#define HD 64
#define NL 4
#define NA 6158
#define NG 64
#define WPAD 68

// dynamic smem layout for k_layer (floats):
//  Wls [0,4352) | Wrs [4352,8704) | bls [8704,8768) | stA [8768,17472) | stH [17472,26176)
#define OFF_WLS 0
#define OFF_WRS 4352
#define OFF_BLS 8704
#define OFF_STA 8768
#define OFF_STH 17472
#define LAYER_SMEM_FLOATS 26176
#define LAYER_SMEM_BYTES (LAYER_SMEM_FLOATS * 4)

// ---------------- scratch (device globals; no allocation allowed) -------------
// NOTE: d_deg is zeroed at the END of each launch (by k_pool) for the next
// graph replay; statically zero-initialized for the first call.
__device__ int   d_flag;
__device__ int   d_src[NE];
__device__ int   d_dst[NE];
__device__ int   d_batch32[NN];
__device__ int   d_deg[NN];
__device__ int   d_rowptr[NN + 1];
__device__ int   d_cursor[NN];
__device__ int   d_csr[NE];
__device__ float d_invdeg[NN];
__device__ float d_h0[NN * HD];
__device__ float d_h1[NN * HD];
__device__ __half2 d_hh[NN * 32];
__device__ float d_agg[NN * HD];
__device__ float d_gsum[NG * HD];
__device__ int   d_gcnt[NG];
__device__ int   d_part[256];

// ---------------- f32x2 packed-FMA helpers -------------------------------------
__device__ __forceinline__ unsigned long long pack2(float x) {
    unsigned long long r;
    asm("mov.b64 %0, {%1, %1};" : "=l"(r) : "f"(x));
    return r;
}
__device__ __forceinline__ void ffma2(unsigned long long& d,
                                      unsigned long long a,
                                      unsigned long long b) {
    asm("fma.rn.f32x2 %0, %1, %2, %0;" : "+l"(d) : "l"(a), "l"(b));
}
__device__ __forceinline__ void unpack2(unsigned long long v, float& lo, float& hi) {
    asm("mov.b64 {%0, %1}, %2;" : "=f"(lo), "=f"(hi) : "l"(v));
}

// convert edges + degree count; dtype detection done block-locally (warp ballot)
__global__ void k_convert_edges(const void* edge) {
    __shared__ int sflag;
    if (threadIdx.x < 32) {
        const unsigned int* w = (const unsigned int*)edge;
        unsigned int m0 = __ballot_sync(0xffffffffu, w[2 * threadIdx.x + 1] == 0u);
        unsigned int m1 = __ballot_sync(0xffffffffu, w[2 * (threadIdx.x + 32) + 1] == 0u);
        if (threadIdx.x == 0) {
            int f = (__popc(m0) + __popc(m1) >= 60) ? 1 : 0;
            sflag = f;
            if (blockIdx.x == 0) d_flag = f;
        }
    }
    __syncthreads();
    int i = blockIdx.x * blockDim.x + threadIdx.x;
    if (i >= 2 * NE) return;
    int v;
    if (sflag) v = (int)((const long long*)edge)[i];
    else       v = ((const int*)edge)[i];
    if (i < NE) d_src[i] = v;
    else        { d_dst[i - NE] = v; atomicAdd(&d_deg[v], 1); }
}

// ---------------- CSR build (scan over degrees) --------------------------------
__global__ void k_scan_a() {
    __shared__ int ts[256];
    int b = blockIdx.x, t = threadIdx.x;
    int base = b * 1024 + t * 4;
    int v[4];
    int s = 0;
#pragma unroll
    for (int j = 0; j < 4; j++) {
        int idx = base + j;
        v[j] = (idx < NN) ? d_deg[idx] : 0;
        s += v[j];
    }
    ts[t] = s;
    __syncthreads();
    for (int off = 1; off < 256; off <<= 1) {
        int x = (t >= off) ? ts[t - off] : 0;
        __syncthreads();
        ts[t] += x;
        __syncthreads();
    }
    int run = ts[t] - s;
#pragma unroll
    for (int j = 0; j < 4; j++) {
        int idx = base + j;
        if (idx < NN) d_rowptr[idx] = run;
        run += v[j];
    }
    if (t == 255) d_part[b] = ts[255];
}

// scan finalize + invdeg + batch conversion
__global__ void k_scan_c(const void* batch) {
    __shared__ int ps[128];
    int t = threadIdx.x;
    int orig = (t < 98) ? d_part[t] : 0;
    if (t < 128) ps[t] = orig;
    __syncthreads();
    for (int off = 1; off < 128; off <<= 1) {
        int x = (t >= off && t < 128) ? ps[t - off] : 0;
        __syncthreads();
        if (t < 128) ps[t] += x;
        __syncthreads();
    }
    if (t < 128) ps[t] -= orig;   // exclusive
    __syncthreads();

    int i = blockIdx.x * blockDim.x + t;
    if (i == 0) d_rowptr[NN] = NE;
    if (i >= NN) return;
    int r = d_rowptr[i] + ps[i >> 10];
    d_rowptr[i] = r;
    d_cursor[i] = r;
    d_invdeg[i] = 1.0f / fmaxf((float)d_deg[i], 1.0f);
    int b;
    if (d_flag) b = (int)((const long long*)batch)[i];
    else        b = ((const int*)batch)[i];
    d_batch32[i] = b;
}

// scatter edges into CSR; also zeroes gsum/gcnt (consumed later this launch)
__global__ void k_scatter() {
    int e = blockIdx.x * blockDim.x + threadIdx.x;
    if (e < NG * HD) d_gsum[e] = 0.f;
    if (e < NG) d_gcnt[e] = 0;
    if (e >= NE) return;
    int dd = d_dst[e];
    int pos = atomicAdd(&d_cursor[dd], 1);
    d_csr[pos] = d_src[e];
}

// ---------------- encoder: h0 = relu(x @ W_enc^T + b_enc) ----------------------
__global__ void k_encoder(const float* __restrict__ x,
                          const float* __restrict__ Wenc,
                          const float* __restrict__ benc) {
    __shared__ float Ws[FIN * HD];
    __shared__ float bs[HD];
    int t = threadIdx.x;
    int gid = blockIdx.x * blockDim.x + t;
    for (int i = t; i < HD * FIN; i += blockDim.x) {
        int j = i / FIN, k = i % FIN;
        Ws[k * HD + j] = Wenc[i];
    }
    if (t < HD) bs[t] = benc[t];
    __syncthreads();
    if (gid >= NN * 32) return;
    int n = gid >> 5, j2 = gid & 31;
    int j = 2 * j2;
    const float* xr = x + n * FIN;
    float a0 = bs[j], a1 = bs[j + 1];
#pragma unroll
    for (int k = 0; k < FIN; k += 4) {
        float4 xv = *(const float4*)(xr + k);
        float2 w0 = *(const float2*)(&Ws[k * HD + j]);
        float2 w1 = *(const float2*)(&Ws[(k + 1) * HD + j]);
        float2 w2 = *(const float2*)(&Ws[(k + 2) * HD + j]);
        float2 w3 = *(const float2*)(&Ws[(k + 3) * HD + j]);
        a0 += xv.x * w0.x + xv.y * w1.x + xv.z * w2.x + xv.w * w3.x;
        a1 += xv.x * w0.y + xv.y * w1.y + xv.z * w2.y + xv.w * w3.y;
    }
    a0 = fmaxf(a0, 0.f);
    a1 = fmaxf(a1, 0.f);
    ((float2*)d_h0)[gid] = make_float2(a0, a1);
    d_hh[gid] = __floats2half2_rn(a0, a1);
}

// ---------------- aggregation: agg[n] = mean_{e: dst=n} h_fp16[src[e]] ---------
__global__ void k_aggregate() {
    int w = (blockIdx.x * blockDim.x + threadIdx.x) >> 5;
    if (w >= NN) return;
    int lane = threadIdx.x & 31;
    int beg = d_rowptr[w], end = d_rowptr[w + 1];
    const __half2* __restrict__ hp = d_hh;
    float ax0 = 0.f, ay0 = 0.f, ax1 = 0.f, ay1 = 0.f;
    int i = beg;
    for (; i + 8 <= end; i += 8) {
        int s0 = d_csr[i + 0], s1 = d_csr[i + 1], s2 = d_csr[i + 2], s3 = d_csr[i + 3];
        int s4 = d_csr[i + 4], s5 = d_csr[i + 5], s6 = d_csr[i + 6], s7 = d_csr[i + 7];
        float2 v0 = __half22float2(hp[s0 * 32 + lane]);
        float2 v1 = __half22float2(hp[s1 * 32 + lane]);
        float2 v2 = __half22float2(hp[s2 * 32 + lane]);
        float2 v3 = __half22float2(hp[s3 * 32 + lane]);
        float2 v4 = __half22float2(hp[s4 * 32 + lane]);
        float2 v5 = __half22float2(hp[s5 * 32 + lane]);
        float2 v6 = __half22float2(hp[s6 * 32 + lane]);
        float2 v7 = __half22float2(hp[s7 * 32 + lane]);
        ax0 += v0.x + v1.x + v2.x + v3.x;
        ay0 += v0.y + v1.y + v2.y + v3.y;
        ax1 += v4.x + v5.x + v6.x + v7.x;
        ay1 += v4.y + v5.y + v6.y + v7.y;
    }
    for (; i < end; i++) {
        float2 v = __half22float2(hp[d_csr[i] * 32 + lane]);
        ax0 += v.x; ay0 += v.y;
    }
    float id = d_invdeg[w];
    ((float2*)d_agg)[w * 32 + lane] = make_float2((ax0 + ax1) * id, (ay0 + ay1) * id);
}

// ---------------- layer v5: smem-staged inputs, fully coalesced gmem ------------
// 128 nodes/block. Thread = (p = t&63 -> nodes p & p+64; jq = t>>6 -> j quarter).
// agg/h rows coop-loaded coalesced into pad-68 smem; LDS reads conflict-free.
__global__ void __launch_bounds__(256, 2)
k_layer(int mode, int write_hh,
        const float* __restrict__ Wl, const float* __restrict__ bl,
        const float* __restrict__ Wr) {
    const float* h    = (mode == 1) ? d_h1 : d_h0;
    float*       hout = (mode == 0) ? d_h1 : d_h0;
    extern __shared__ float S[];
    float* Wls = S + OFF_WLS;
    float* Wrs = S + OFF_WRS;
    float* bls = S + OFF_BLS;
    float* stA = S + OFF_STA;
    float* stH = S + OFF_STH;
    int t = threadIdx.x;
    int base = blockIdx.x * 128;

    for (int i = t; i < HD * HD; i += 256) {
        int j = i >> 6, k = i & 63;
        Wls[k * WPAD + j] = Wl[i];
        Wrs[k * WPAD + j] = Wr[i];
    }
    if (t < HD) bls[t] = bl[t];

    // coop-load agg & h rows (contiguous gmem, coalesced) into padded smem
    for (int i = t; i < 2048; i += 256) {
        int row = i >> 4, f = i & 15;
        int gn = base + row;
        if (gn < NN) {
            *(float4*)&stA[row * WPAD + f * 4] = ((const float4*)(d_agg + gn * 64))[f];
            *(float4*)&stH[row * WPAD + f * 4] = ((const float4*)(h + gn * 64))[f];
        }
    }
    __syncthreads();

    int p  = t & 63;
    int jq = t >> 6;   // 0..3, j slice [16*jq, 16*jq+16)
    int n0 = base + p, n1 = base + 64 + p;
    bool v0 = (n0 < NN), v1 = (n1 < NN);

    unsigned long long accA[8], accB[8];
    {
        const unsigned long long* bp2 = (const unsigned long long*)(bls + jq * 16);
#pragma unroll
        for (int q = 0; q < 8; q++) { accA[q] = bp2[q]; accB[q] = bp2[q]; }
    }

#pragma unroll 2
    for (int k4 = 0; k4 < 16; k4++) {
        float4 aA = *(const float4*)&stA[p * WPAD + k4 * 4];
        float4 hA = *(const float4*)&stH[p * WPAD + k4 * 4];
        float4 aB = *(const float4*)&stA[(p + 64) * WPAD + k4 * 4];
        float4 hB = *(const float4*)&stH[(p + 64) * WPAD + k4 * 4];
        float aAv[4] = {aA.x, aA.y, aA.z, aA.w};
        float hAv[4] = {hA.x, hA.y, hA.z, hA.w};
        float aBv[4] = {aB.x, aB.y, aB.z, aB.w};
        float hBv[4] = {hB.x, hB.y, hB.z, hB.w};
#pragma unroll
        for (int kk = 0; kk < 4; kk++) {
            int k = k4 * 4 + kk;
            const ulonglong2* __restrict__ wl =
                (const ulonglong2*)(Wls + k * WPAD + jq * 16);
            const ulonglong2* __restrict__ wr =
                (const ulonglong2*)(Wrs + k * WPAD + jq * 16);
            unsigned long long aAp = pack2(aAv[kk]);
            unsigned long long hAp = pack2(hAv[kk]);
            unsigned long long aBp = pack2(aBv[kk]);
            unsigned long long hBp = pack2(hBv[kk]);
#pragma unroll
            for (int j2 = 0; j2 < 4; j2++) {
                ulonglong2 L = wl[j2];
                ulonglong2 R = wr[j2];
                ffma2(accA[2 * j2 + 0], aAp, L.x);
                ffma2(accA[2 * j2 + 1], aAp, L.y);
                ffma2(accA[2 * j2 + 0], hAp, R.x);
                ffma2(accA[2 * j2 + 1], hAp, R.y);
                ffma2(accB[2 * j2 + 0], aBp, L.x);
                ffma2(accB[2 * j2 + 1], aBp, L.y);
                ffma2(accB[2 * j2 + 0], hBp, R.x);
                ffma2(accB[2 * j2 + 1], hBp, R.y);
            }
        }
    }

    // epilogue: relu + residual (residual from stH, still intact), stage into stA
    float o[16];
#pragma unroll
    for (int q = 0; q < 8; q++) unpack2(accA[q], o[2 * q], o[2 * q + 1]);
    {
        const float4* res = (const float4*)&stH[p * WPAD + jq * 16];
#pragma unroll
        for (int f = 0; f < 4; f++) {
            float4 r = res[f];
            o[4 * f + 0] = fmaxf(o[4 * f + 0], 0.f) + r.x;
            o[4 * f + 1] = fmaxf(o[4 * f + 1], 0.f) + r.y;
            o[4 * f + 2] = fmaxf(o[4 * f + 2], 0.f) + r.z;
            o[4 * f + 3] = fmaxf(o[4 * f + 3], 0.f) + r.w;
        }
    }
    float o1[16];
#pragma unroll
    for (int q = 0; q < 8; q++) unpack2(accB[q], o1[2 * q], o1[2 * q + 1]);
    {
        const float4* res = (const float4*)&stH[(p + 64) * WPAD + jq * 16];
#pragma unroll
        for (int f = 0; f < 4; f++) {
            float4 r = res[f];
            o1[4 * f + 0] = fmaxf(o1[4 * f + 0], 0.f) + r.x;
            o1[4 * f + 1] = fmaxf(o1[4 * f + 1], 0.f) + r.y;
            o1[4 * f + 2] = fmaxf(o1[4 * f + 2], 0.f) + r.z;
            o1[4 * f + 3] = fmaxf(o1[4 * f + 3], 0.f) + r.w;
        }
    }
    __syncthreads();   // all stA reads done -> safe to overwrite
    {
        float4* s0 = (float4*)&stA[p * WPAD + jq * 16];
        float4* s1 = (float4*)&stA[(p + 64) * WPAD + jq * 16];
#pragma unroll
        for (int f = 0; f < 4; f++) {
            s0[f] = make_float4(o[4 * f], o[4 * f + 1], o[4 * f + 2], o[4 * f + 3]);
            s1[f] = make_float4(o1[4 * f], o1[4 * f + 1], o1[4 * f + 2], o1[4 * f + 3]);
        }
    }
    __syncthreads();
    // coop copy out (coalesced): 128 nodes x 16 float4
    for (int i = t; i < 2048; i += 256) {
        int row = i >> 4, f = i & 15;
        int gn = base + row;
        if (gn < NN) {
            float4 vv = *(const float4*)&stA[row * WPAD + f * 4];
            *(float4*)(hout + gn * 64 + f * 4) = vv;
            if (write_hh) {
                __half2 l2 = __floats2half2_rn(vv.x, vv.y);
                __half2 h2 = __floats2half2_rn(vv.z, vv.w);
                unsigned int ul = *(unsigned int*)&l2;
                unsigned int uh = *(unsigned int*)&h2;
                ((uint2*)d_hh)[gn * 16 + f] = make_uint2(ul, uh);
            }
        }
    }
    (void)v0; (void)v1;
}

// ---------------- global mean pool (coalesced) + gcnt + deg re-zero -------------
__global__ void k_pool(int sel) {
    int tid = blockIdx.x * blockDim.x + threadIdx.x;
    int z = tid * 2;
    if (z < NN) {
        d_deg[z] = 0;
        if (z + 1 < NN) d_deg[z + 1] = 0;
    }

    const float* __restrict__ h = sel ? d_h1 : d_h0;
    int warp = threadIdx.x >> 5, lane = threadIdx.x & 31;
    int rbase = blockIdx.x * 512 + warp * 64;
    if (rbase >= NN) return;
    int rowoff = lane >> 4;
    int f4 = lane & 15;
    float a0 = 0.f, a1 = 0.f, a2 = 0.f, a3 = 0.f;
    int cnt = 0;
    int cur = -1;
    for (int it = 0; it < 32; it++) {
        int row = rbase + it * 2 + rowoff;
        if (row >= NN) break;
        int b = d_batch32[row];
        if (b != cur) {
            if (cur >= 0) {
                atomicAdd(&d_gsum[cur * HD + f4 * 4 + 0], a0);
                atomicAdd(&d_gsum[cur * HD + f4 * 4 + 1], a1);
                atomicAdd(&d_gsum[cur * HD + f4 * 4 + 2], a2);
                atomicAdd(&d_gsum[cur * HD + f4 * 4 + 3], a3);
                if (f4 == 0) atomicAdd(&d_gcnt[cur], cnt);
            }
            a0 = a1 = a2 = a3 = 0.f;
            cnt = 0;
            cur = b;
        }
        float4 v = *(const float4*)(h + row * HD + f4 * 4);
        a0 += v.x; a1 += v.y; a2 += v.z; a3 += v.w;
        cnt++;
    }
    if (cur >= 0) {
        atomicAdd(&d_gsum[cur * HD + f4 * 4 + 0], a0);
        atomicAdd(&d_gsum[cur * HD + f4 * 4 + 1], a1);
        atomicAdd(&d_gsum[cur * HD + f4 * 4 + 2], a2);
        atomicAdd(&d_gsum[cur * HD + f4 * 4 + 3], a3);
        if (f4 == 0) atomicAdd(&d_gcnt[cur], cnt);
    }
}

// ---------------- heads: policy (blocks 0..48) + value (last block) -------------
__global__ void __launch_bounds__(128)
k_policy(const float* __restrict__ Wp, const float* __restrict__ bp,
         const float* __restrict__ Wv, const float* __restrict__ bv,
         float* __restrict__ out) {
    __shared__ float repr[NG * HD];
    int t = threadIdx.x;
    for (int i = t; i < NG * HD; i += 128) {
        int g = i >> 6;
        repr[i] = d_gsum[i] / fmaxf((float)d_gcnt[g], 1.f);
    }
    __syncthreads();

    if (blockIdx.x == gridDim.x - 1) {   // value head
        int g = t;
        if (g >= NG) return;
        float acc = 0.f;
#pragma unroll
        for (int k = 0; k < HD; k++) acc += repr[g * HD + k] * Wv[k];
        out[NG * NA + g] = tanhf(acc + bv[0]);
        return;
    }

    int a = blockIdx.x * 128 + t;
    if (a >= NA) return;
    float acc[NG];
#pragma unroll
    for (int g = 0; g < NG; g++) acc[g] = 0.f;
    const float4* __restrict__ wr = (const float4*)(Wp + a * HD);
#pragma unroll 2
    for (int k4 = 0; k4 < 16; k4++) {
        float4 w = wr[k4];
#pragma unroll
        for (int g = 0; g < NG; g++) {
            float4 r = *(const float4*)(&repr[g * HD + k4 * 4]);
            acc[g] += w.x * r.x + w.y * r.y + w.z * r.z + w.w * r.w;
        }
    }
    float bias = bp[a];
#pragma unroll
    for (int g = 0; g < NG; g++) out[g * NA + a] = acc[g] + bias;
}

// ---------------- launcher -----------------------------------------------------
extern "C" void kernel_launch(void* const* d_in, const int* in_sizes, int n_in,
                              void* d_out, int out_size) {
    const float* x     = (const float*)d_in[0];
    const void*  edge  = d_in[1];
    const void*  batch = d_in[2];
    const float* Wenc  = (const float*)d_in[3];
    const float* benc  = (const float*)d_in[4];
    const float* Wl    = (const float*)d_in[5];
    const float* bl    = (const float*)d_in[6];
    const float* Wr    = (const float*)d_in[7];
    const float* Wp    = (const float*)d_in[8];
    const float* bp    = (const float*)d_in[9];
    const float* Wv    = (const float*)d_in[10];
    const float* bv    = (const float*)d_in[11];
    float* out = (float*)d_out;

    // allow >48KB dynamic smem for k_layer (idempotent; not a stream op)
    cudaFuncSetAttribute(k_layer, cudaFuncAttributeMaxDynamicSharedMemorySize,
                         LAYER_SMEM_BYTES);

    k_convert_edges<<<(2 * NE + 255) / 256, 256>>>(edge);          // idx 0
    k_scan_a<<<98, 256>>>();                                       // idx 1
    k_scan_c<<<(NN + 255) / 256, 256>>>(batch);                    // idx 2
    k_scatter<<<(NE + 255) / 256, 256>>>();                        // idx 3 (profiled)
    k_encoder<<<(NN * 32 + 255) / 256, 256>>>(x, Wenc, benc);      // idx 4

    for (int i = 0; i < NL; i++) {
        k_aggregate<<<(NN * 32 + 255) / 256, 256>>>();
        k_layer<<<(NN + 127) / 128, 256, LAYER_SMEM_BYTES>>>(
            i & 1, (i < NL - 1) ? 1 : 0,
            Wl + i * HD * HD, bl + i * HD, Wr + i * HD * HD);
    }

    k_pool<<<(NN + 511) / 512, 256>>>(0);   // final h is d_h0 after 4 layers
    k_policy<<<(NA + 127) / 128 + 1, 128>>>(Wp, bp, Wv, bv, out);
}

// round 14
// speedup vs baseline: 1.2167x; 1.0134x over previous
#include <cuda_runtime.h>
#include <cuda_fp16.h>
#include <math.h>

#define NN 100000
#define NE 3200000
#define FIN 32
#define HD 64
#define NL 4
#define NA 6158
#define NG 64
#define WPAD 68

// dynamic smem layout for k_layer (floats):
//  Wls [0,4352) | Wrs [4352,8704) | bls [8704,8768) | stA [8768,17472) | stH [17472,26176)
#define OFF_WLS 0
#define OFF_WRS 4352
#define OFF_BLS 8704
#define OFF_STA 8768
#define OFF_STH 17472
#define LAYER_SMEM_FLOATS 26176
#define LAYER_SMEM_BYTES (LAYER_SMEM_FLOATS * 4)

// ---------------- scratch (device globals; no allocation allowed) -------------
// NOTE: d_deg is zeroed at the END of each launch (by k_pool) for the next
// graph replay; statically zero-initialized for the first call.
__device__ int   d_flag;
__device__ int   d_batch32[NN];
__device__ int   d_deg[NN];
__device__ int   d_rowptr[NN + 1];
__device__ int   d_cursor[NN];
__device__ int   d_csr[NE];
__device__ float d_invdeg[NN];
__device__ float d_h0[NN * HD];
__device__ float d_h1[NN * HD];
__device__ __half2 d_hh[NN * 32];      // fp16 copy of current h (gather source)
__device__ __half2 d_agg16[NN * 32];   // fp16 aggregate (layer input)
__device__ float d_gsum[NG * HD];
__device__ int   d_gcnt[NG];
__device__ int   d_part[256];

// ---------------- f32x2 packed-FMA helpers -------------------------------------
__device__ __forceinline__ unsigned long long pack2(float x) {
    unsigned long long r;
    asm("mov.b64 %0, {%1, %1};" : "=l"(r) : "f"(x));
    return r;
}
__device__ __forceinline__ void ffma2(unsigned long long& d,
                                      unsigned long long a,
                                      unsigned long long b) {
    asm("fma.rn.f32x2 %0, %1, %2, %0;" : "+l"(d) : "l"(a), "l"(b));
}
__device__ __forceinline__ void unpack2(unsigned long long v, float& lo, float& hi) {
    asm("mov.b64 {%0, %1}, %2;" : "=f"(lo), "=f"(hi) : "l"(v));
}

// ---------------- degree count straight from edge dst half ----------------------
__global__ void k_degree(const void* edge) {
    __shared__ int sflag;
    if (threadIdx.x < 32) {
        const unsigned int* w = (const unsigned int*)edge;
        unsigned int m0 = __ballot_sync(0xffffffffu, w[2 * threadIdx.x + 1] == 0u);
        unsigned int m1 = __ballot_sync(0xffffffffu, w[2 * (threadIdx.x + 32) + 1] == 0u);
        if (threadIdx.x == 0) {
            int f = (__popc(m0) + __popc(m1) >= 60) ? 1 : 0;
            sflag = f;
            if (blockIdx.x == 0) d_flag = f;   // for k_scan_c / k_scatter
        }
    }
    __syncthreads();
    int e = blockIdx.x * blockDim.x + threadIdx.x;
    if (e >= NE) return;
    int dd;
    if (sflag) dd = (int)((const long long*)edge)[NE + e];
    else       dd = ((const int*)edge)[NE + e];
    atomicAdd(&d_deg[dd], 1);
}

// ---------------- CSR build (scan over degrees) --------------------------------
__global__ void k_scan_a() {
    __shared__ int ts[256];
    int b = blockIdx.x, t = threadIdx.x;
    int base = b * 1024 + t * 4;
    int v[4];
    int s = 0;
#pragma unroll
    for (int j = 0; j < 4; j++) {
        int idx = base + j;
        v[j] = (idx < NN) ? d_deg[idx] : 0;
        s += v[j];
    }
    ts[t] = s;
    __syncthreads();
    for (int off = 1; off < 256; off <<= 1) {
        int x = (t >= off) ? ts[t - off] : 0;
        __syncthreads();
        ts[t] += x;
        __syncthreads();
    }
    int run = ts[t] - s;
#pragma unroll
    for (int j = 0; j < 4; j++) {
        int idx = base + j;
        if (idx < NN) d_rowptr[idx] = run;
        run += v[j];
    }
    if (t == 255) d_part[b] = ts[255];
}

// scan finalize + invdeg + batch conversion
__global__ void k_scan_c(const void* batch) {
    __shared__ int ps[128];
    int t = threadIdx.x;
    int orig = (t < 98) ? d_part[t] : 0;
    if (t < 128) ps[t] = orig;
    __syncthreads();
    for (int off = 1; off < 128; off <<= 1) {
        int x = (t >= off && t < 128) ? ps[t - off] : 0;
        __syncthreads();
        if (t < 128) ps[t] += x;
        __syncthreads();
    }
    if (t < 128) ps[t] -= orig;   // exclusive
    __syncthreads();

    int i = blockIdx.x * blockDim.x + t;
    if (i == 0) d_rowptr[NN] = NE;
    if (i >= NN) return;
    int r = d_rowptr[i] + ps[i >> 10];
    d_rowptr[i] = r;
    d_cursor[i] = r;
    d_invdeg[i] = 1.0f / fmaxf((float)d_deg[i], 1.0f);
    int b;
    if (d_flag) b = (int)((const long long*)batch)[i];
    else        b = ((const int*)batch)[i];
    d_batch32[i] = b;
}

// scatter edges into CSR, converting src/dst inline; zeroes gsum/gcnt
__global__ void k_scatter(const void* edge) {
    int e = blockIdx.x * blockDim.x + threadIdx.x;
    if (e < NG * HD) d_gsum[e] = 0.f;
    if (e < NG) d_gcnt[e] = 0;
    if (e >= NE) return;
    int ss, dd;
    if (d_flag) {
        ss = (int)((const long long*)edge)[e];
        dd = (int)((const long long*)edge)[NE + e];
    } else {
        ss = ((const int*)edge)[e];
        dd = ((const int*)edge)[NE + e];
    }
    int pos = atomicAdd(&d_cursor[dd], 1);
    d_csr[pos] = ss;
}

// ---------------- encoder: h0 = relu(x @ W_enc^T + b_enc) ----------------------
__global__ void k_encoder(const float* __restrict__ x,
                          const float* __restrict__ Wenc,
                          const float* __restrict__ benc) {
    __shared__ float Ws[FIN * HD];
    __shared__ float bs[HD];
    int t = threadIdx.x;
    int gid = blockIdx.x * blockDim.x + t;
    for (int i = t; i < HD * FIN; i += blockDim.x) {
        int j = i / FIN, k = i % FIN;
        Ws[k * HD + j] = Wenc[i];
    }
    if (t < HD) bs[t] = benc[t];
    __syncthreads();
    if (gid >= NN * 32) return;
    int n = gid >> 5, j2 = gid & 31;
    int j = 2 * j2;
    const float* xr = x + n * FIN;
    float a0 = bs[j], a1 = bs[j + 1];
#pragma unroll
    for (int k = 0; k < FIN; k += 4) {
        float4 xv = *(const float4*)(xr + k);
        float2 w0 = *(const float2*)(&Ws[k * HD + j]);
        float2 w1 = *(const float2*)(&Ws[(k + 1) * HD + j]);
        float2 w2 = *(const float2*)(&Ws[(k + 2) * HD + j]);
        float2 w3 = *(const float2*)(&Ws[(k + 3) * HD + j]);
        a0 += xv.x * w0.x + xv.y * w1.x + xv.z * w2.x + xv.w * w3.x;
        a1 += xv.x * w0.y + xv.y * w1.y + xv.z * w2.y + xv.w * w3.y;
    }
    a0 = fmaxf(a0, 0.f);
    a1 = fmaxf(a1, 0.f);
    ((float2*)d_h0)[gid] = make_float2(a0, a1);
    d_hh[gid] = __floats2half2_rn(a0, a1);
}

// ---------------- aggregation -> fp16: agg16[n] = mean_{e: dst=n} h_fp16[src] --
__global__ void k_aggregate() {
    int w = (blockIdx.x * blockDim.x + threadIdx.x) >> 5;
    if (w >= NN) return;
    int lane = threadIdx.x & 31;
    int beg = d_rowptr[w], end = d_rowptr[w + 1];
    const __half2* __restrict__ hp = d_hh;
    float ax0 = 0.f, ay0 = 0.f, ax1 = 0.f, ay1 = 0.f;
    int i = beg;
    for (; i + 8 <= end; i += 8) {
        int s0 = d_csr[i + 0], s1 = d_csr[i + 1], s2 = d_csr[i + 2], s3 = d_csr[i + 3];
        int s4 = d_csr[i + 4], s5 = d_csr[i + 5], s6 = d_csr[i + 6], s7 = d_csr[i + 7];
        float2 v0 = __half22float2(hp[s0 * 32 + lane]);
        float2 v1 = __half22float2(hp[s1 * 32 + lane]);
        float2 v2 = __half22float2(hp[s2 * 32 + lane]);
        float2 v3 = __half22float2(hp[s3 * 32 + lane]);
        float2 v4 = __half22float2(hp[s4 * 32 + lane]);
        float2 v5 = __half22float2(hp[s5 * 32 + lane]);
        float2 v6 = __half22float2(hp[s6 * 32 + lane]);
        float2 v7 = __half22float2(hp[s7 * 32 + lane]);
        ax0 += v0.x + v1.x + v2.x + v3.x;
        ay0 += v0.y + v1.y + v2.y + v3.y;
        ax1 += v4.x + v5.x + v6.x + v7.x;
        ay1 += v4.y + v5.y + v6.y + v7.y;
    }
    for (; i < end; i++) {
        float2 v = __half22float2(hp[d_csr[i] * 32 + lane]);
        ax0 += v.x; ay0 += v.y;
    }
    float id = d_invdeg[w];
    d_agg16[w * 32 + lane] = __floats2half2_rn((ax0 + ax1) * id, (ay0 + ay1) * id);
}

// ---------------- layer v6: fp16 agg input, smem-staged, coalesced --------------
__global__ void __launch_bounds__(256, 2)
k_layer(int mode, int write_hh,
        const float* __restrict__ Wl, const float* __restrict__ bl,
        const float* __restrict__ Wr) {
    const float* h    = (mode == 1) ? d_h1 : d_h0;
    float*       hout = (mode == 0) ? d_h1 : d_h0;
    extern __shared__ float S[];
    float* Wls = S + OFF_WLS;
    float* Wrs = S + OFF_WRS;
    float* bls = S + OFF_BLS;
    float* stA = S + OFF_STA;
    float* stH = S + OFF_STH;
    int t = threadIdx.x;
    int base = blockIdx.x * 128;

    for (int i = t; i < HD * HD; i += 256) {
        int j = i >> 6, k = i & 63;
        Wls[k * WPAD + j] = Wl[i];
        Wrs[k * WPAD + j] = Wr[i];
    }
    if (t < HD) bls[t] = bl[t];

    // coop-load h rows fp32 (coalesced) and agg rows fp16 -> fp32 stage
    for (int i = t; i < 2048; i += 256) {
        int row = i >> 4, f = i & 15;
        int gn = base + row;
        if (gn < NN)
            *(float4*)&stH[row * WPAD + f * 4] = ((const float4*)(h + gn * 64))[f];
    }
    for (int i = t; i < 1024; i += 256) {       // 128 rows x 8 uint4 (16B fp16 = 8 floats)
        int row = i >> 3, f = i & 7;
        int gn = base + row;
        if (gn < NN) {
            uint4 q = ((const uint4*)(d_agg16 + gn * 32))[f];
            const __half2* hq = (const __half2*)&q;
            float2 f0 = __half22float2(hq[0]);
            float2 f1 = __half22float2(hq[1]);
            float2 f2 = __half22float2(hq[2]);
            float2 f3 = __half22float2(hq[3]);
            float* dst = &stA[row * WPAD + f * 8];
            *(float4*)(dst)     = make_float4(f0.x, f0.y, f1.x, f1.y);
            *(float4*)(dst + 4) = make_float4(f2.x, f2.y, f3.x, f3.y);
        }
    }
    __syncthreads();

    int p  = t & 63;
    int jq = t >> 6;   // 0..3, j slice [16*jq, 16*jq+16)

    unsigned long long accA[8], accB[8];
    {
        const unsigned long long* bp2 = (const unsigned long long*)(bls + jq * 16);
#pragma unroll
        for (int q = 0; q < 8; q++) { accA[q] = bp2[q]; accB[q] = bp2[q]; }
    }

#pragma unroll 2
    for (int k4 = 0; k4 < 16; k4++) {
        float4 aA = *(const float4*)&stA[p * WPAD + k4 * 4];
        float4 hA = *(const float4*)&stH[p * WPAD + k4 * 4];
        float4 aB = *(const float4*)&stA[(p + 64) * WPAD + k4 * 4];
        float4 hB = *(const float4*)&stH[(p + 64) * WPAD + k4 * 4];
        float aAv[4] = {aA.x, aA.y, aA.z, aA.w};
        float hAv[4] = {hA.x, hA.y, hA.z, hA.w};
        float aBv[4] = {aB.x, aB.y, aB.z, aB.w};
        float hBv[4] = {hB.x, hB.y, hB.z, hB.w};
#pragma unroll
        for (int kk = 0; kk < 4; kk++) {
            int k = k4 * 4 + kk;
            const ulonglong2* __restrict__ wl =
                (const ulonglong2*)(Wls + k * WPAD + jq * 16);
            const ulonglong2* __restrict__ wr =
                (const ulonglong2*)(Wrs + k * WPAD + jq * 16);
            unsigned long long aAp = pack2(aAv[kk]);
            unsigned long long hAp = pack2(hAv[kk]);
            unsigned long long aBp = pack2(aBv[kk]);
            unsigned long long hBp = pack2(hBv[kk]);
#pragma unroll
            for (int j2 = 0; j2 < 4; j2++) {
                ulonglong2 L = wl[j2];
                ulonglong2 R = wr[j2];
                ffma2(accA[2 * j2 + 0], aAp, L.x);
                ffma2(accA[2 * j2 + 1], aAp, L.y);
                ffma2(accA[2 * j2 + 0], hAp, R.x);
                ffma2(accA[2 * j2 + 1], hAp, R.y);
                ffma2(accB[2 * j2 + 0], aBp, L.x);
                ffma2(accB[2 * j2 + 1], aBp, L.y);
                ffma2(accB[2 * j2 + 0], hBp, R.x);
                ffma2(accB[2 * j2 + 1], hBp, R.y);
            }
        }
    }

    // epilogue: relu + residual (stH intact), stage into stA, copy out coalesced
    float o[16];
#pragma unroll
    for (int q = 0; q < 8; q++) unpack2(accA[q], o[2 * q], o[2 * q + 1]);
    {
        const float4* res = (const float4*)&stH[p * WPAD + jq * 16];
#pragma unroll
        for (int f = 0; f < 4; f++) {
            float4 r = res[f];
            o[4 * f + 0] = fmaxf(o[4 * f + 0], 0.f) + r.x;
            o[4 * f + 1] = fmaxf(o[4 * f + 1], 0.f) + r.y;
            o[4 * f + 2] = fmaxf(o[4 * f + 2], 0.f) + r.z;
            o[4 * f + 3] = fmaxf(o[4 * f + 3], 0.f) + r.w;
        }
    }
    float o1[16];
#pragma unroll
    for (int q = 0; q < 8; q++) unpack2(accB[q], o1[2 * q], o1[2 * q + 1]);
    {
        const float4* res = (const float4*)&stH[(p + 64) * WPAD + jq * 16];
#pragma unroll
        for (int f = 0; f < 4; f++) {
            float4 r = res[f];
            o1[4 * f + 0] = fmaxf(o1[4 * f + 0], 0.f) + r.x;
            o1[4 * f + 1] = fmaxf(o1[4 * f + 1], 0.f) + r.y;
            o1[4 * f + 2] = fmaxf(o1[4 * f + 2], 0.f) + r.z;
            o1[4 * f + 3] = fmaxf(o1[4 * f + 3], 0.f) + r.w;
        }
    }
    __syncthreads();   // all stA reads done -> safe to overwrite
    {
        float4* s0 = (float4*)&stA[p * WPAD + jq * 16];
        float4* s1 = (float4*)&stA[(p + 64) * WPAD + jq * 16];
#pragma unroll
        for (int f = 0; f < 4; f++) {
            s0[f] = make_float4(o[4 * f], o[4 * f + 1], o[4 * f + 2], o[4 * f + 3]);
            s1[f] = make_float4(o1[4 * f], o1[4 * f + 1], o1[4 * f + 2], o1[4 * f + 3]);
        }
    }
    __syncthreads();
    for (int i = t; i < 2048; i += 256) {
        int row = i >> 4, f = i & 15;
        int gn = base + row;
        if (gn < NN) {
            float4 vv = *(const float4*)&stA[row * WPAD + f * 4];
            *(float4*)(hout + gn * 64 + f * 4) = vv;
            if (write_hh) {
                __half2 l2 = __floats2half2_rn(vv.x, vv.y);
                __half2 h2 = __floats2half2_rn(vv.z, vv.w);
                unsigned int ul = *(unsigned int*)&l2;
                unsigned int uh = *(unsigned int*)&h2;
                ((uint2*)d_hh)[gn * 16 + f] = make_uint2(ul, uh);
            }
        }
    }
}

// ---------------- global mean pool (coalesced) + gcnt + deg re-zero -------------
__global__ void k_pool(int sel) {
    int tid = blockIdx.x * blockDim.x + threadIdx.x;
    int z = tid * 2;
    if (z < NN) {
        d_deg[z] = 0;
        if (z + 1 < NN) d_deg[z + 1] = 0;
    }

    const float* __restrict__ h = sel ? d_h1 : d_h0;
    int warp = threadIdx.x >> 5, lane = threadIdx.x & 31;
    int rbase = blockIdx.x * 512 + warp * 64;
    if (rbase >= NN) return;
    int rowoff = lane >> 4;
    int f4 = lane & 15;
    float a0 = 0.f, a1 = 0.f, a2 = 0.f, a3 = 0.f;
    int cnt = 0;
    int cur = -1;
    for (int it = 0; it < 32; it++) {
        int row = rbase + it * 2 + rowoff;
        if (row >= NN) break;
        int b = d_batch32[row];
        if (b != cur) {
            if (cur >= 0) {
                atomicAdd(&d_gsum[cur * HD + f4 * 4 + 0], a0);
                atomicAdd(&d_gsum[cur * HD + f4 * 4 + 1], a1);
                atomicAdd(&d_gsum[cur * HD + f4 * 4 + 2], a2);
                atomicAdd(&d_gsum[cur * HD + f4 * 4 + 3], a3);
                if (f4 == 0) atomicAdd(&d_gcnt[cur], cnt);
            }
            a0 = a1 = a2 = a3 = 0.f;
            cnt = 0;
            cur = b;
        }
        float4 v = *(const float4*)(h + row * HD + f4 * 4);
        a0 += v.x; a1 += v.y; a2 += v.z; a3 += v.w;
        cnt++;
    }
    if (cur >= 0) {
        atomicAdd(&d_gsum[cur * HD + f4 * 4 + 0], a0);
        atomicAdd(&d_gsum[cur * HD + f4 * 4 + 1], a1);
        atomicAdd(&d_gsum[cur * HD + f4 * 4 + 2], a2);
        atomicAdd(&d_gsum[cur * HD + f4 * 4 + 3], a3);
        if (f4 == 0) atomicAdd(&d_gcnt[cur], cnt);
    }
}

// ---------------- heads: policy (blocks 0..48) + value (last block) -------------
__global__ void __launch_bounds__(128)
k_policy(const float* __restrict__ Wp, const float* __restrict__ bp,
         const float* __restrict__ Wv, const float* __restrict__ bv,
         float* __restrict__ out) {
    __shared__ float repr[NG * HD];
    int t = threadIdx.x;
    for (int i = t; i < NG * HD; i += 128) {
        int g = i >> 6;
        repr[i] = d_gsum[i] / fmaxf((float)d_gcnt[g], 1.f);
    }
    __syncthreads();

    if (blockIdx.x == gridDim.x - 1) {   // value head
        int g = t;
        if (g >= NG) return;
        float acc = 0.f;
#pragma unroll
        for (int k = 0; k < HD; k++) acc += repr[g * HD + k] * Wv[k];
        out[NG * NA + g] = tanhf(acc + bv[0]);
        return;
    }

    int a = blockIdx.x * 128 + t;
    if (a >= NA) return;
    float acc[NG];
#pragma unroll
    for (int g = 0; g < NG; g++) acc[g] = 0.f;
    const float4* __restrict__ wr = (const float4*)(Wp + a * HD);
#pragma unroll 2
    for (int k4 = 0; k4 < 16; k4++) {
        float4 w = wr[k4];
#pragma unroll
        for (int g = 0; g < NG; g++) {
            float4 r = *(const float4*)(&repr[g * HD + k4 * 4]);
            acc[g] += w.x * r.x + w.y * r.y + w.z * r.z + w.w * r.w;
        }
    }
    float bias = bp[a];
#pragma unroll
    for (int g = 0; g < NG; g++) out[g * NA + a] = acc[g] + bias;
}

// ---------------- launcher -----------------------------------------------------
extern "C" void kernel_launch(void* const* d_in, const int* in_sizes, int n_in,
                              void* d_out, int out_size) {
    const float* x     = (const float*)d_in[0];
    const void*  edge  = d_in[1];
    const void*  batch = d_in[2];
    const float* Wenc  = (const float*)d_in[3];
    const float* benc  = (const float*)d_in[4];
    const float* Wl    = (const float*)d_in[5];
    const float* bl    = (const float*)d_in[6];
    const float* Wr    = (const float*)d_in[7];
    const float* Wp    = (const float*)d_in[8];
    const float* bp    = (const float*)d_in[9];
    const float* Wv    = (const float*)d_in[10];
    const float* bv    = (const float*)d_in[11];
    float* out = (float*)d_out;

    cudaFuncSetAttribute(k_layer, cudaFuncAttributeMaxDynamicSharedMemorySize,
                         LAYER_SMEM_BYTES);

    k_degree<<<(NE + 255) / 256, 256>>>(edge);                     // idx 0
    k_scan_a<<<98, 256>>>();                                       // idx 1
    k_scan_c<<<(NN + 255) / 256, 256>>>(batch);                    // idx 2
    k_scatter<<<(NE + 255) / 256, 256>>>(edge);                    // idx 3 (profiled)
    k_encoder<<<(NN * 32 + 255) / 256, 256>>>(x, Wenc, benc);      // idx 4

    for (int i = 0; i < NL; i++) {
        k_aggregate<<<(NN * 32 + 255) / 256, 256>>>();
        k_layer<<<(NN + 127) / 128, 256, LAYER_SMEM_BYTES>>>(
            i & 1, (i < NL - 1) ? 1 : 0,
            Wl + i * HD * HD, bl + i * HD, Wr + i * HD * HD);
    }

    k_pool<<<(NN + 511) / 512, 256>>>(0);   // final h is d_h0 after 4 layers
    k_policy<<<(NA + 127) / 128 + 1, 128>>>(Wp, bp, Wv, bv, out);
}